// round 12
// baseline (speedup 1.0000x reference)
#include <cuda_runtime.h>
#include <cuda_bf16.h>
#include <math.h>

// ---------------------------------------------------------------------------
// GritLM pooling: masked segment mean over tokens + L2 normalize per sequence.
// Inputs (metadata order):
//   d_in[0] : float32 hidden_states [TOTAL, D]
//   d_in[1] : int32   prompt_lens   [B]
//   d_in[2] : int32   instruction_lens [B]
// Output: float32 [B, D]
//
// FINAL configuration (machine floor):
// Stage 1: one CTA (1024 threads) owns full 16KB rows of one sequence chunk
//          -> perfectly contiguous DRAM streams, 144 CTAs = single wave.
//          Measured at ~6.37 TB/s = the B300 full-chip stream cap; the
//          512 MB mandatory read bounds the kernel at ~80.4 us.
// Stage 2: fused reduce + mean + L2 normalize (16 CTAs, PDL, no atomics,
//          fully deterministic).
// ---------------------------------------------------------------------------

#define TSPLIT 9
#define MAX_B  64
#define MAX_D  8192
// Static device scratch (runtime allocs forbidden).
__device__ float g_part[(size_t)TSPLIT * MAX_B * MAX_D];

__device__ __forceinline__ float4 ldcs4(const float* p) {
    return __ldcs((const float4*)p);
}

// ---------------------------------------------------------------------------
// Kernel 1: contiguous-row partial sums.
// grid: (TSPLIT, B), block: 1024 threads. Thread t owns columns t*4..t*4+3.
// 8x row unroll -> 8 outstanding LDG.128 per thread (128 KB in flight / SM);
// rows contiguous so each CTA is one long sequential stream.
// ---------------------------------------------------------------------------
__global__ __launch_bounds__(1024, 1)
void pool_partial_kernel(const float* __restrict__ hs,
                         const int* __restrict__ plen,
                         const int* __restrict__ ilen,
                         int B, int D)
{
    const int split = blockIdx.x;
    const int b     = blockIdx.y;
    const int c     = threadIdx.x * 4;

    long long start = 0;
    for (int i = 0; i < b; i++) start += (long long)plen[i];
    const int len  = plen[b];
    const int inst = ilen[b];

    const int chunk = (len + TSPLIT - 1) / TSPLIT;
    int r0 = split * chunk;
    int r1 = r0 + chunk; if (r1 > len) r1 = len;
    if (r0 < inst) r0 = inst;        // mask instruction tokens

    float4 acc = make_float4(0.f, 0.f, 0.f, 0.f);

    if (c < D && r0 < r1) {
        const float* base = hs + (start + (long long)r0) * (long long)D + c;
        const long long stride = D;
        int r = r0;
        for (; r + 7 < r1; r += 8) {     // MLP=8; rows contiguous in DRAM
            float4 v0 = ldcs4(base);
            float4 v1 = ldcs4(base + stride);
            float4 v2 = ldcs4(base + 2 * stride);
            float4 v3 = ldcs4(base + 3 * stride);
            float4 v4 = ldcs4(base + 4 * stride);
            float4 v5 = ldcs4(base + 5 * stride);
            float4 v6 = ldcs4(base + 6 * stride);
            float4 v7 = ldcs4(base + 7 * stride);
            float sx0 = v0.x + v1.x, sx1 = v2.x + v3.x, sx2 = v4.x + v5.x, sx3 = v6.x + v7.x;
            float sy0 = v0.y + v1.y, sy1 = v2.y + v3.y, sy2 = v4.y + v5.y, sy3 = v6.y + v7.y;
            float sz0 = v0.z + v1.z, sz1 = v2.z + v3.z, sz2 = v4.z + v5.z, sz3 = v6.z + v7.z;
            float sw0 = v0.w + v1.w, sw1 = v2.w + v3.w, sw2 = v4.w + v5.w, sw3 = v6.w + v7.w;
            acc.x += (sx0 + sx1) + (sx2 + sx3);
            acc.y += (sy0 + sy1) + (sy2 + sy3);
            acc.z += (sz0 + sz1) + (sz2 + sz3);
            acc.w += (sw0 + sw1) + (sw2 + sw3);
            base += 8 * stride;
        }
        for (; r < r1; r++) {
            float4 v = ldcs4(base);
            acc.x += v.x; acc.y += v.y; acc.z += v.z; acc.w += v.w;
            base += stride;
        }
    }

    if (c < D) {
        float* p = &g_part[((size_t)split * B + b) * (size_t)D + c];
        *(float4*)p = acc;
    }

    // Let the dependent (PDL) kernel start as soon as possible.
    cudaTriggerProgrammaticLaunchCompletion();
}

// ---------------------------------------------------------------------------
// Kernel 2 (fused, PDL): reduce TSPLIT partials -> mean -> L2 normalize.
// One block per sequence; blockDim.x == D/4 (one float4 per thread).
// Fixed-order sums -> deterministic; no atomics; graph-replay safe.
// ---------------------------------------------------------------------------
__global__ __launch_bounds__(1024)
void mean_norm_kernel(const int* __restrict__ plen,
                      const int* __restrict__ ilen,
                      float* __restrict__ out,
                      int B, int D)
{
    const int b = blockIdx.x;
    const int c = threadIdx.x * 4;

    // k1-independent prologue (overlaps k1 tail under PDL)
    const float inv = 1.0f / (float)(plen[b] - ilen[b]);
    const float* pp = &g_part[(size_t)b * D + c];

    cudaGridDependencySynchronize();

    float4 s = make_float4(0.f, 0.f, 0.f, 0.f);
    if (c < D) {
#pragma unroll
        for (int t = 0; t < TSPLIT; t++) {
            const float4 v = *(const float4*)(pp + (size_t)t * B * D);
            s.x += v.x; s.y += v.y; s.z += v.z; s.w += v.w;
        }
        s.x *= inv; s.y *= inv; s.z *= inv; s.w *= inv;
    }

    // block-reduce sum of squares of the mean vector
    float ss = s.x * s.x + s.y * s.y + s.z * s.z + s.w * s.w;
    __shared__ float sm[32];
    for (int off = 16; off > 0; off >>= 1)
        ss += __shfl_down_sync(0xFFFFFFFFu, ss, off);
    const int lane = threadIdx.x & 31, wid = threadIdx.x >> 5;
    if (lane == 0) sm[wid] = ss;
    __syncthreads();
    const int nwarps = (blockDim.x + 31) >> 5;
    if (wid == 0) {
        float v = (lane < nwarps) ? sm[lane] : 0.f;
        for (int off = 16; off > 0; off >>= 1)
            v += __shfl_down_sync(0xFFFFFFFFu, v, off);
        if (lane == 0) sm[0] = v;
    }
    __syncthreads();

    const float norm = fmaxf(sqrtf(sm[0]), 1e-12f);
    const float inv_n = 1.0f / norm;

    if (c < D) {
        s.x *= inv_n; s.y *= inv_n; s.z *= inv_n; s.w *= inv_n;
        *(float4*)(out + (size_t)b * D + c) = s;
    }
}

// ---------------------------------------------------------------------------
extern "C" void kernel_launch(void* const* d_in, const int* in_sizes, int n_in,
                              void* d_out, int out_size)
{
    const float* hs   = (const float*)d_in[0];
    const int*   plen = (const int*)d_in[1];
    const int*   ilen = (const int*)d_in[2];
    float*       out  = (float*)d_out;

    const int B = in_sizes[1];
    const int D = out_size / B;   // 4096

    // Stage 1: contiguous-row partial sums (144 CTAs = one wave).
    dim3 grid1(TSPLIT, B);
    pool_partial_kernel<<<grid1, 1024>>>(hs, plen, ilen, B, D);

    // Stage 2: fused reduce + mean + L2 normalize, PDL-overlapped.
    int threads = D / 4;            // 1024 for D=4096
    if (threads > 1024) threads = 1024;

    cudaLaunchConfig_t cfg = {};
    cfg.gridDim  = dim3(B, 1, 1);
    cfg.blockDim = dim3(threads, 1, 1);
    cfg.dynamicSmemBytes = 0;
    cfg.stream = 0;
    cudaLaunchAttribute attrs[1];
    attrs[0].id = cudaLaunchAttributeProgrammaticStreamSerialization;
    attrs[0].val.programmaticStreamSerializationAllowed = 1;
    cfg.attrs = attrs;
    cfg.numAttrs = 1;
    cudaLaunchKernelEx(&cfg, mean_norm_kernel, plen, ilen, out, B, D);
}

// round 13
// speedup vs baseline: 1.0050x; 1.0050x over previous
#include <cuda_runtime.h>
#include <cuda_bf16.h>
#include <math.h>

// ---------------------------------------------------------------------------
// GritLM pooling: masked segment mean over tokens + L2 normalize per sequence.
// Inputs (metadata order):
//   d_in[0] : float32 hidden_states [TOTAL, D]
//   d_in[1] : int32   prompt_lens   [B]
//   d_in[2] : int32   instruction_lens [B]
// Output: float32 [B, D]
//
// Stage 1: 512-thread CTAs, 2 CTAs/SM (288 CTAs = one wave on 144 SMs).
//          Each CTA owns full contiguous 16KB rows (512 thr x 2 float4 = D);
//          second resident CTA covers the first one's drain/exit tail.
// Stage 2: fused reduce + mean + L2 normalize (16 CTAs, PDL, no atomics).
// ---------------------------------------------------------------------------

#define TSPLIT 18
#define MAX_B  64
#define MAX_D  8192
// Static device scratch (runtime allocs forbidden).
__device__ float g_part[(size_t)TSPLIT * MAX_B * MAX_D];

__device__ __forceinline__ float4 ldcs4(const float* p) {
    return __ldcs((const float4*)p);
}

// ---------------------------------------------------------------------------
// Kernel 1: contiguous-row partial sums, 2 CTAs/SM.
// grid: (TSPLIT, B), block: 512 threads. Thread t owns two float4 columns:
// t*4 and 2048 + t*4 (full 4096-float row per CTA).
// 4x row unroll x 2 columns -> 8 outstanding LDG.128 per thread.
// ---------------------------------------------------------------------------
__global__ __launch_bounds__(512, 2)
void pool_partial_kernel(const float* __restrict__ hs,
                         const int* __restrict__ plen,
                         const int* __restrict__ ilen,
                         int B, int D)
{
    const int split = blockIdx.x;
    const int b     = blockIdx.y;
    const int half  = D / 2;                    // 2048 for D=4096
    const int c0    = threadIdx.x * 4;          // first column
    const int c1    = half + threadIdx.x * 4;   // second column

    long long start = 0;
    for (int i = 0; i < b; i++) start += (long long)plen[i];
    const int len  = plen[b];
    const int inst = ilen[b];

    const int chunk = (len + TSPLIT - 1) / TSPLIT;
    int r0 = split * chunk;
    int r1 = r0 + chunk; if (r1 > len) r1 = len;
    if (r0 < inst) r0 = inst;        // mask instruction tokens

    float4 a0 = make_float4(0.f, 0.f, 0.f, 0.f);
    float4 a1 = make_float4(0.f, 0.f, 0.f, 0.f);

    if (c0 < half && r0 < r1) {
        const float* base = hs + (start + (long long)r0) * (long long)D;
        const long long stride = D;
        int r = r0;
        // 4x row unroll x 2 columns = 8 outstanding LDG.128 per thread
        for (; r + 3 < r1; r += 4) {
            float4 u0 = ldcs4(base + c0);
            float4 w0 = ldcs4(base + c1);
            float4 u1 = ldcs4(base + stride + c0);
            float4 w1 = ldcs4(base + stride + c1);
            float4 u2 = ldcs4(base + 2 * stride + c0);
            float4 w2 = ldcs4(base + 2 * stride + c1);
            float4 u3 = ldcs4(base + 3 * stride + c0);
            float4 w3 = ldcs4(base + 3 * stride + c1);
            a0.x += (u0.x + u1.x) + (u2.x + u3.x);
            a0.y += (u0.y + u1.y) + (u2.y + u3.y);
            a0.z += (u0.z + u1.z) + (u2.z + u3.z);
            a0.w += (u0.w + u1.w) + (u2.w + u3.w);
            a1.x += (w0.x + w1.x) + (w2.x + w3.x);
            a1.y += (w0.y + w1.y) + (w2.y + w3.y);
            a1.z += (w0.z + w1.z) + (w2.z + w3.z);
            a1.w += (w0.w + w1.w) + (w2.w + w3.w);
            base += 4 * stride;
        }
        for (; r < r1; r++) {
            float4 u = ldcs4(base + c0);
            float4 w = ldcs4(base + c1);
            a0.x += u.x; a0.y += u.y; a0.z += u.z; a0.w += u.w;
            a1.x += w.x; a1.y += w.y; a1.z += w.z; a1.w += w.w;
            base += stride;
        }
    }

    if (c0 < half) {
        float* p = &g_part[((size_t)split * B + b) * (size_t)D];
        *(float4*)(p + c0) = a0;
        *(float4*)(p + c1) = a1;
    }

    // Let the dependent (PDL) kernel start as soon as possible.
    cudaTriggerProgrammaticLaunchCompletion();
}

// ---------------------------------------------------------------------------
// Kernel 2 (fused, PDL): reduce TSPLIT partials -> mean -> L2 normalize.
// One block per sequence; blockDim.x == D/4 (one float4 per thread).
// Fixed-order sums -> deterministic; no atomics; graph-replay safe.
// ---------------------------------------------------------------------------
__global__ __launch_bounds__(1024)
void mean_norm_kernel(const int* __restrict__ plen,
                      const int* __restrict__ ilen,
                      float* __restrict__ out,
                      int B, int D)
{
    const int b = blockIdx.x;
    const int c = threadIdx.x * 4;

    // k1-independent prologue (overlaps k1 tail under PDL)
    const float inv = 1.0f / (float)(plen[b] - ilen[b]);
    const float* pp = &g_part[(size_t)b * D + c];

    cudaGridDependencySynchronize();

    float4 s = make_float4(0.f, 0.f, 0.f, 0.f);
    if (c < D) {
#pragma unroll
        for (int t = 0; t < TSPLIT; t++) {
            const float4 v = *(const float4*)(pp + (size_t)t * B * D);
            s.x += v.x; s.y += v.y; s.z += v.z; s.w += v.w;
        }
        s.x *= inv; s.y *= inv; s.z *= inv; s.w *= inv;
    }

    // block-reduce sum of squares of the mean vector
    float ss = s.x * s.x + s.y * s.y + s.z * s.z + s.w * s.w;
    __shared__ float sm[32];
    for (int off = 16; off > 0; off >>= 1)
        ss += __shfl_down_sync(0xFFFFFFFFu, ss, off);
    const int lane = threadIdx.x & 31, wid = threadIdx.x >> 5;
    if (lane == 0) sm[wid] = ss;
    __syncthreads();
    const int nwarps = (blockDim.x + 31) >> 5;
    if (wid == 0) {
        float v = (lane < nwarps) ? sm[lane] : 0.f;
        for (int off = 16; off > 0; off >>= 1)
            v += __shfl_down_sync(0xFFFFFFFFu, v, off);
        if (lane == 0) sm[0] = v;
    }
    __syncthreads();

    const float norm = fmaxf(sqrtf(sm[0]), 1e-12f);
    const float inv_n = 1.0f / norm;

    if (c < D) {
        s.x *= inv_n; s.y *= inv_n; s.z *= inv_n; s.w *= inv_n;
        *(float4*)(out + (size_t)b * D + c) = s;
    }
}

// ---------------------------------------------------------------------------
extern "C" void kernel_launch(void* const* d_in, const int* in_sizes, int n_in,
                              void* d_out, int out_size)
{
    const float* hs   = (const float*)d_in[0];
    const int*   plen = (const int*)d_in[1];
    const int*   ilen = (const int*)d_in[2];
    float*       out  = (float*)d_out;

    const int B = in_sizes[1];
    const int D = out_size / B;   // 4096

    // Stage 1: contiguous-row partial sums (288 CTAs = 2/SM, one wave).
    dim3 grid1(TSPLIT, B);
    pool_partial_kernel<<<grid1, 512>>>(hs, plen, ilen, B, D);

    // Stage 2: fused reduce + mean + L2 normalize, PDL-overlapped.
    int threads = D / 4;            // 1024 for D=4096
    if (threads > 1024) threads = 1024;

    cudaLaunchConfig_t cfg = {};
    cfg.gridDim  = dim3(B, 1, 1);
    cfg.blockDim = dim3(threads, 1, 1);
    cfg.dynamicSmemBytes = 0;
    cfg.stream = 0;
    cudaLaunchAttribute attrs[1];
    attrs[0].id = cudaLaunchAttributeProgrammaticStreamSerialization;
    attrs[0].val.programmaticStreamSerializationAllowed = 1;
    cfg.attrs = attrs;
    cfg.numAttrs = 1;
    cudaLaunchKernelEx(&cfg, mean_norm_kernel, plen, ilen, out, B, D);
}